// round 4
// baseline (speedup 1.0000x reference)
#include <cuda_runtime.h>

#define BQ 256
#define NQ 512
#define EQ 64
#define OQ 64
#define KQ 8
#define NT 64            // n-tile per block
#define NBLK (NQ / NT)   // 8 n-blocks per batch

// Scratch (device globals: allocation-free rule)
__device__ float g_priors[BQ * NQ * OQ];           // 33.5 MB [b][n][o]
__device__ float g_s[BQ * NQ * KQ];                // 4 MB    [b][n][k] cumulative logit shift
__device__ float g_zpart[NBLK * BQ * KQ * OQ];     // 4 MB    [slot][b][k][o]
__device__ float g_v[BQ * KQ * OQ];                // 0.5 MB  [b][k][o]

// ---------------------------------------------------------------------------
// Phase C: stream cc (float4 over o), softmax over K, accumulate z, then
// log-tree reduce the 16 n-lanes in smem (reusing p_sm) and write one
// z-partial per block. 256 threads = 16 o-quads x 16 n-lanes.
// ---------------------------------------------------------------------------
template <bool HAS_S>
__device__ __forceinline__ void phase_c(const float* __restrict__ cc,
                                        float* p_sm, const float* s_sm,
                                        int tid, int b, int n0, int slot) {
    int o = (tid & 15) << 2;       // o-quad base
    int nlane = tid >> 4;          // 0..15
    const float* base = cc + ((size_t)b * (KQ * NQ) + n0) * OQ + o;

    float acc[8][4];
#pragma unroll
    for (int k = 0; k < 8; k++) {
        acc[k][0] = 0.f; acc[k][1] = 0.f; acc[k][2] = 0.f; acc[k][3] = 0.f;
    }

#pragma unroll
    for (int i = 0; i < 4; i++) {
        int nl = nlane + (i << 4);
        const float* p = base + nl * OQ;
        float ta[4][8];
#pragma unroll
        for (int k = 0; k < 8; k++) {
            float4 t = *(const float4*)(p + (size_t)k * (NQ * OQ));
            float sk = HAS_S ? s_sm[nl * 8 + k] : 0.f;
            ta[0][k] = t.x + sk; ta[1][k] = t.y + sk;
            ta[2][k] = t.z + sk; ta[3][k] = t.w + sk;
        }
        float4 pr4 = *(const float4*)&p_sm[nl * 68 + o];
        float prc[4] = {pr4.x, pr4.y, pr4.z, pr4.w};
#pragma unroll
        for (int c = 0; c < 4; c++) {
            float m = ta[c][0];
#pragma unroll
            for (int k = 1; k < 8; k++) m = fmaxf(m, ta[c][k]);
            float e[8], d = 0.f;
#pragma unroll
            for (int k = 0; k < 8; k++) { e[k] = __expf(ta[c][k] - m); d += e[k]; }
            float w = prc[c] * __fdividef(1.f, d);
#pragma unroll
            for (int k = 0; k < 8; k++) acc[k][c] = fmaf(e[k], w, acc[k][c]);
        }
    }

    // tree-reduce 16 n-lanes -> 1, reusing p_sm (needs 8*512=4096 <= 64*68 floats)
#pragma unroll
    for (int half = 8; half >= 1; half >>= 1) {
        __syncthreads();           // readers of p_sm / prior stage done
        if (nlane >= half && nlane < 2 * half) {
#pragma unroll
            for (int k = 0; k < 8; k++) {
                float4 v = make_float4(acc[k][0], acc[k][1], acc[k][2], acc[k][3]);
                *(float4*)&p_sm[(nlane - half) * 512 + k * 64 + o] = v;
            }
        }
        __syncthreads();
        if (nlane < half) {
#pragma unroll
            for (int k = 0; k < 8; k++) {
                float4 v = *(const float4*)&p_sm[nlane * 512 + k * 64 + o];
                acc[k][0] += v.x; acc[k][1] += v.y; acc[k][2] += v.z; acc[k][3] += v.w;
            }
        }
    }
    if (nlane == 0) {
        float* zp = g_zpart + ((size_t)slot * BQ + b) * (KQ * OQ) + o;
#pragma unroll
        for (int k = 0; k < 8; k++) {
            float4 v = make_float4(acc[k][0], acc[k][1], acc[k][2], acc[k][3]);
            *(float4*)&zp[k * 64] = v;
        }
    }
}

// ---------------------------------------------------------------------------
// Pass 0: fused tile-GEMM (priors = emb @ S) + Phase C (no shift).
// Also writes priors tile to g_priors for passes 1/2.
// ---------------------------------------------------------------------------
__global__ __launch_bounds__(256) void pass0_kernel(const float* __restrict__ emb,
                                                    const float* __restrict__ S,
                                                    const float* __restrict__ cc) {
    __shared__ float sm_a[64 * 68];   // At[e][n], later reused as p_sm + reduce buf
    __shared__ float sm_b[64 * 68];   // S[e][o]
    int tid = threadIdx.x;
    int b = blockIdx.y, n0 = blockIdx.x * NT;

    const float4* a4 = (const float4*)(emb + ((size_t)b * NQ + n0) * EQ);
    for (int i = tid; i < 1024; i += 256) {
        float4 v = a4[i];
        int nl = i >> 4, e = (i & 15) << 2;
        sm_a[(e + 0) * 68 + nl] = v.x;
        sm_a[(e + 1) * 68 + nl] = v.y;
        sm_a[(e + 2) * 68 + nl] = v.z;
        sm_a[(e + 3) * 68 + nl] = v.w;
    }
    const float4* s4 = (const float4*)S;
    for (int i = tid; i < 1024; i += 256) {
        float4 v = s4[i];
        int e = i >> 4, o = (i & 15) << 2;
        float* r = &sm_b[e * 68 + o];
        r[0] = v.x; r[1] = v.y; r[2] = v.z; r[3] = v.w;
    }
    __syncthreads();

    int ty = tid >> 4, tx = tid & 15;     // n-group, o-group
    float pacc[4][4] = {};
#pragma unroll 16
    for (int e = 0; e < 64; e++) {
        float af[4], bf[4];
        *(float4*)af = *(const float4*)&sm_a[e * 68 + ty * 4];
        *(float4*)bf = *(const float4*)&sm_b[e * 68 + tx * 4];
#pragma unroll
        for (int i2 = 0; i2 < 4; i2++)
#pragma unroll
            for (int j = 0; j < 4; j++)
                pacc[i2][j] = fmaf(af[i2], bf[j], pacc[i2][j]);
    }
    __syncthreads();   // all At reads done before overwrite

    float* gp = g_priors + ((size_t)b * NQ + n0) * OQ;
#pragma unroll
    for (int i2 = 0; i2 < 4; i2++) {
        int nl = ty * 4 + i2;
        float4 v = make_float4(pacc[i2][0], pacc[i2][1], pacc[i2][2], pacc[i2][3]);
        *(float4*)&sm_a[nl * 68 + tx * 4] = v;
        *(float4*)&gp[(size_t)nl * 64 + tx * 4] = v;
    }
    __syncthreads();

    phase_c<false>(cc, sm_a, nullptr, tid, b, n0, blockIdx.x);
}

// ---------------------------------------------------------------------------
// Passes 1/2: load priors tile + v, compute shifts (fused sim), Phase C.
// MODE 1: s = sim(v), write g_s.  MODE 2: s = g_s + sim(v).
// ---------------------------------------------------------------------------
template <int MODE>
__global__ __launch_bounds__(256) void pass_kernel(const float* __restrict__ cc) {
    __shared__ float p_sm[64 * 68];
    __shared__ float s_sm[64 * 8];
    __shared__ float v_sm[64 * 8];   // [o][k]
    int tid = threadIdx.x;
    int b = blockIdx.y, n0 = blockIdx.x * NT;

    const float4* psrc = (const float4*)(g_priors + ((size_t)b * NQ + n0) * OQ);
    for (int i = tid; i < 1024; i += 256) {
        float4 v = psrc[i];
        int nl = i >> 4, o = (i & 15) << 2;
        *(float4*)&p_sm[nl * 68 + o] = v;
    }
    for (int i = tid; i < 512; i += 256) {
        float vv = g_v[(size_t)b * 512 + i];
        int k = i >> 6, o = i & 63;
        v_sm[o * 8 + k] = vv;
    }
    __syncthreads();

    // shifts: s[nl][k] = dot(p[nl,:], v[:,k]) (+ g_s for MODE 2)
    {
        int nl = tid >> 2;
        int k2 = (tid & 3) << 1;
        const float* prow = &p_sm[nl * 68];
        float a0 = 0.f, a1 = 0.f;
#pragma unroll
        for (int o = 0; o < 64; o++) {
            float pv = prow[o];
            float2 vv = *(const float2*)&v_sm[o * 8 + k2];
            a0 = fmaf(pv, vv.x, a0);
            a1 = fmaf(pv, vv.y, a1);
        }
        size_t sidx = ((size_t)b * NQ + n0 + nl) * 8 + k2;
        if (MODE == 2) {
            float2 sp = *(const float2*)&g_s[sidx];
            a0 += sp.x; a1 += sp.y;
        }
        float2 r = make_float2(a0, a1);
        *(float2*)&s_sm[nl * 8 + k2] = r;
        if (MODE == 1) *(float2*)&g_s[sidx] = r;
    }
    __syncthreads();

    phase_c<true>(cc, p_sm, s_sm, tid, b, n0, blockIdx.x);
}

// ---------------------------------------------------------------------------
// squash: sum the 8 z partials; v = (||z||^2/(1+||z||^2)) * z / sqrt(||z||^2+eps)
// One warp per (b,k) vector of length 64.
// ---------------------------------------------------------------------------
template <bool FINAL>
__global__ __launch_bounds__(256) void squash_kernel(float* __restrict__ out) {
    int w = (blockIdx.x * 256 + threadIdx.x) >> 5;    // 0..2047 = b*8+k
    int lane = threadIdx.x & 31;
    const int SL = BQ * KQ * OQ;                      // 131072
    int base = w * 64;

    float z0 = 0.f, z1 = 0.f;
#pragma unroll
    for (int s = 0; s < NBLK; s++) {
        z0 += g_zpart[(size_t)s * SL + base + lane];
        z1 += g_zpart[(size_t)s * SL + base + lane + 32];
    }

    float sq = z0 * z0 + z1 * z1;
#pragma unroll
    for (int off = 16; off; off >>= 1) sq += __shfl_xor_sync(0xffffffffu, sq, off);

    float denom = (1.0f + sq) * __fsqrt_rn(sq + 1e-9f);
    float f = __fdiv_rn(sq, denom);

    float* dst = FINAL ? out : g_v;
    dst[base + lane] = z0 * f;
    dst[base + lane + 32] = z1 * f;
}

// ---------------------------------------------------------------------------
extern "C" void kernel_launch(void* const* d_in, const int* in_sizes, int n_in,
                              void* d_out, int out_size) {
    const float* emb = (const float*)d_in[0];
    const float* S   = (const float*)d_in[1];
    const float* cc  = (const float*)d_in[2];
    for (int i = 0; i < n_in; i++) {
        if (in_sizes[i] == BQ * NQ * EQ)            emb = (const float*)d_in[i];
        else if (in_sizes[i] == EQ * OQ)            S = (const float*)d_in[i];
        else if (in_sizes[i] == BQ * KQ * NQ * OQ)  cc = (const float*)d_in[i];
    }
    float* out = (float*)d_out;

    dim3 pg(NBLK, BQ);
    pass0_kernel<<<pg, 256>>>(emb, S, cc);
    squash_kernel<false><<<256, 256>>>(nullptr);

    pass_kernel<1><<<pg, 256>>>(cc);
    squash_kernel<false><<<256, 256>>>(nullptr);

    pass_kernel<2><<<pg, 256>>>(cc);
    squash_kernel<true><<<256, 256>>>(out);
}

// round 6
// speedup vs baseline: 1.1831x; 1.1831x over previous
#include <cuda_runtime.h>

#define BQ 256
#define NQ 512
#define EQ 64
#define OQ 64
#define KQ 8

// Scratch (device globals: allocation-free rule)
__device__ float g_priors[BQ * NQ * OQ];        // 33.5 MB  [b][n][o]
__device__ float g_s[BQ * NQ * KQ];             // 4 MB     [b][n][k]  cumulative logit shift
__device__ float g_zpart[4 * BQ * KQ * OQ];     // 2 MB     [slot][b][k][o]
__device__ float g_v[BQ * KQ * OQ];             // 0.5 MB   [b][k][o]

// ---------------------------------------------------------------------------
// priors = emb @ S : (131072 x 64) @ (64 x 64), fp32
// ---------------------------------------------------------------------------
__global__ __launch_bounds__(256) void gemm_kernel(const float* __restrict__ A,
                                                   const float* __restrict__ S) {
    __shared__ float At[64 * 68];
    __shared__ float Bs[64 * 68];

    int tid = threadIdx.x;
    size_t row0 = (size_t)blockIdx.x * 64;

    const float4* a4 = (const float4*)(A + row0 * 64);
    for (int i = tid; i < 1024; i += 256) {
        float4 v = a4[i];
        int r = i >> 4, c = (i & 15) << 2;
        At[(c + 0) * 68 + r] = v.x;
        At[(c + 1) * 68 + r] = v.y;
        At[(c + 2) * 68 + r] = v.z;
        At[(c + 3) * 68 + r] = v.w;
    }
    const float4* b4 = (const float4*)S;
    for (int i = tid; i < 1024; i += 256) {
        float4 v = b4[i];
        int e = i >> 4, c = (i & 15) << 2;
        float* row = &Bs[e * 68 + c];
        row[0] = v.x; row[1] = v.y; row[2] = v.z; row[3] = v.w;
    }
    __syncthreads();

    int ty = tid >> 4, tx = tid & 15;
    float acc[4][4] = {};
#pragma unroll 16
    for (int e = 0; e < 64; e++) {
        float af[4], bf[4];
        *(float4*)af = *(const float4*)&At[e * 68 + ty * 4];
        *(float4*)bf = *(const float4*)&Bs[e * 68 + tx * 4];
#pragma unroll
        for (int i = 0; i < 4; i++)
#pragma unroll
            for (int j = 0; j < 4; j++)
                acc[i][j] = fmaf(af[i], bf[j], acc[i][j]);
    }
#pragma unroll
    for (int i = 0; i < 4; i++) {
        float4 v = make_float4(acc[i][0], acc[i][1], acc[i][2], acc[i][3]);
        *(float4*)&g_priors[(row0 + ty * 4 + i) * 64 + tx * 4] = v;
    }
}

// ---------------------------------------------------------------------------
// Routing pass: one block = (b, 128-n slice).
//   MODE 0: s = 0            MODE 1: s = sim(v), write g_s
//   MODE 2: s = g_s + sim(v)
// Phase C: 256 threads = 32 o-pairs x 8 n-lanes; float2 cc loads.
// ---------------------------------------------------------------------------
template <int MODE>
__global__ __launch_bounds__(256) void pass_kernel(const float* __restrict__ cc) {
    __shared__ float p_sm[128 * 68];   // priors tile [nl][o] (pad 68); reused for z reduce
    __shared__ float s_sm[128 * 8];    // logit shifts [nl][k]
    __shared__ float v_sm[64 * 8];     // v transposed [o][k]

    int tid = threadIdx.x;
    int b = blockIdx.y;
    int n0 = blockIdx.x * 128;

    // ---- Phase A: stage priors tile (+v) ----
    const float4* psrc = (const float4*)(g_priors + ((size_t)b * NQ + n0) * OQ);
    for (int i4 = tid; i4 < 2048; i4 += 256) {
        float4 v = psrc[i4];
        int nl = i4 >> 4, oc = (i4 & 15) << 2;
        *(float4*)&p_sm[nl * 68 + oc] = v;
    }
    if (MODE != 0) {
        for (int i = tid; i < 512; i += 256) {
            float vv = g_v[(size_t)b * 512 + i];
            int k = i >> 6, o2 = i & 63;
            v_sm[o2 * 8 + k] = vv;
        }
    }
    __syncthreads();

    // ---- Phase B: per-n logit shifts ----
    if (MODE == 0) {
        for (int i = tid; i < 1024; i += 256) s_sm[i] = 0.f;
    } else {
        int nl = tid >> 1;
        int kq = (tid & 1) << 2;
        const float* prow = &p_sm[nl * 68];
        float a0 = 0.f, a1 = 0.f, a2 = 0.f, a3 = 0.f;
#pragma unroll
        for (int o2 = 0; o2 < 64; o2++) {
            float p = prow[o2];
            float4 vv = *(const float4*)&v_sm[o2 * 8 + kq];
            a0 = fmaf(p, vv.x, a0);
            a1 = fmaf(p, vv.y, a1);
            a2 = fmaf(p, vv.z, a2);
            a3 = fmaf(p, vv.w, a3);
        }
        size_t sidx = ((size_t)b * NQ + n0 + nl) * 8 + kq;
        if (MODE == 2) {
            float4 sp = *(const float4*)&g_s[sidx];
            a0 += sp.x; a1 += sp.y; a2 += sp.z; a3 += sp.w;
        }
        float4 res = make_float4(a0, a1, a2, a3);
        *(float4*)&s_sm[nl * 8 + kq] = res;
        if (MODE == 1) *(float4*)&g_s[sidx] = res;
    }
    __syncthreads();

    // ---- Phase C: stream cc (float2 over o), softmax over K, accumulate z ----
    int o = (tid & 31) << 1;          // o-pair base (0..62)
    int nlane = tid >> 5;             // 0..7
    const float* ccb = cc + (size_t)b * (KQ * NQ * OQ);

    float acc[8][2];
#pragma unroll
    for (int k = 0; k < 8; k++) { acc[k][0] = 0.f; acc[k][1] = 0.f; }

#pragma unroll 2
    for (int i = 0; i < 16; i++) {
        int nl = nlane + (i << 3);
        int n = n0 + nl;
        const float* p = ccb + (size_t)n * OQ + o;
        float tx[8], ty_[8];
#pragma unroll
        for (int k = 0; k < 8; k++) {
            float2 t = *(const float2*)(p + (size_t)k * (NQ * OQ));
            float sk = s_sm[nl * 8 + k];
            tx[k] = t.x + sk;
            ty_[k] = t.y + sk;
        }
        float2 pr = *(const float2*)&p_sm[nl * 68 + o];

        float m0 = tx[0], m1 = ty_[0];
#pragma unroll
        for (int k = 1; k < 8; k++) { m0 = fmaxf(m0, tx[k]); m1 = fmaxf(m1, ty_[k]); }
        float e0[8], e1[8], d0 = 0.f, d1 = 0.f;
#pragma unroll
        for (int k = 0; k < 8; k++) {
            e0[k] = __expf(tx[k] - m0); d0 += e0[k];
            e1[k] = __expf(ty_[k] - m1); d1 += e1[k];
        }
        float w0 = pr.x * __fdividef(1.f, d0);
        float w1 = pr.y * __fdividef(1.f, d1);
#pragma unroll
        for (int k = 0; k < 8; k++) {
            acc[k][0] = fmaf(e0[k], w0, acc[k][0]);
            acc[k][1] = fmaf(e1[k], w1, acc[k][1]);
        }
    }

    // ---- one-shot smem reduce: 8 n-lanes -> 1 (reuse p_sm) ----
    __syncthreads();
#pragma unroll
    for (int k = 0; k < 8; k++)
        *(float2*)&p_sm[nlane * 512 + k * 64 + o] = make_float2(acc[k][0], acc[k][1]);
    __syncthreads();
    for (int j = tid; j < 512; j += 256) {
        float z = p_sm[j] + p_sm[512 + j] + p_sm[1024 + j] + p_sm[1536 + j] +
                  p_sm[2048 + j] + p_sm[2560 + j] + p_sm[3072 + j] + p_sm[3584 + j];
        g_zpart[((size_t)blockIdx.x * BQ + b) * (KQ * OQ) + j] = z;
    }
}

// ---------------------------------------------------------------------------
// squash: sum 4 z partials; v = (||z||^2/(1+||z||^2)) * z / sqrt(||z||^2+eps)
// ---------------------------------------------------------------------------
template <bool FINAL>
__global__ __launch_bounds__(256) void squash_kernel(float* __restrict__ out) {
    int w = (blockIdx.x * 256 + threadIdx.x) >> 5;    // 0..2047 = b*8+k
    int lane = threadIdx.x & 31;
    const int SL = BQ * KQ * OQ;                      // 131072
    int base = w * 64;

    float z0 = g_zpart[base + lane] + g_zpart[SL + base + lane] +
               g_zpart[2 * SL + base + lane] + g_zpart[3 * SL + base + lane];
    int l2 = lane + 32;
    float z1 = g_zpart[base + l2] + g_zpart[SL + base + l2] +
               g_zpart[2 * SL + base + l2] + g_zpart[3 * SL + base + l2];

    float sq = z0 * z0 + z1 * z1;
#pragma unroll
    for (int off = 16; off; off >>= 1) sq += __shfl_xor_sync(0xffffffffu, sq, off);

    float denom = (1.0f + sq) * __fsqrt_rn(sq + 1e-9f);
    float f = __fdiv_rn(sq, denom);

    float* dst = FINAL ? out : g_v;
    dst[base + lane] = z0 * f;
    dst[base + l2]  = z1 * f;
}

// ---------------------------------------------------------------------------
extern "C" void kernel_launch(void* const* d_in, const int* in_sizes, int n_in,
                              void* d_out, int out_size) {
    const float* emb = (const float*)d_in[0];
    const float* S   = (const float*)d_in[1];
    const float* cc  = (const float*)d_in[2];
    for (int i = 0; i < n_in; i++) {
        if (in_sizes[i] == BQ * NQ * EQ)            emb = (const float*)d_in[i];
        else if (in_sizes[i] == EQ * OQ)            S = (const float*)d_in[i];
        else if (in_sizes[i] == BQ * KQ * NQ * OQ)  cc = (const float*)d_in[i];
    }
    float* out = (float*)d_out;

    gemm_kernel<<<2048, 256>>>(emb, S);

    dim3 pg(4, BQ);
    pass_kernel<0><<<pg, 256>>>(cc);
    squash_kernel<false><<<256, 256>>>(nullptr);

    pass_kernel<1><<<pg, 256>>>(cc);
    squash_kernel<false><<<256, 256>>>(nullptr);

    pass_kernel<2><<<pg, 256>>>(cc);
    squash_kernel<true><<<256, 256>>>(out);
}